// round 10
// baseline (speedup 1.0000x reference)
#include <cuda_runtime.h>

// QuaternionMaxAmpPool2d — converged R3 shape; this round: __ldcg loads
// (L2-only caching — read stream has zero L1 reuse) + __stcs stores.
//
// x: (16, 256, 128, 128) fp32, c = comp*64 + c4 (comp outer)
// out: (16, 256, 64, 64) fp32
// For each (b, c4, h2, w2): amp2[p] = sum_comp x[b, comp*64+c4, 2h2+kh, 2w2+kw]^2,
// p = kh*2+kw; first argmax p (strict >, sqrt dropped — monotone); emit the 4
// component values at p.
//
// Shape (measured optimal across 9 rounds):
//   - block=256, grid=8192; 2 output pixels per thread (one w2-pair)
//   - per component: 2 front-batched LDG.128 (rows 2h2, 2h2+1); warp spans a
//     full 512B input row per load slot -> perfect coalescing, MLP=8
//   - float2 .cs stores; warp spans 256B contiguous output per component

#define NB   16
#define NC4  64
#define HH   128
#define WW   128
#define H2   64
#define W2   64

__device__ __forceinline__ float pick2x2(const float4& t, const float4& bt, int idx, bool hi) {
    float c0 = hi ? t.z  : t.x;
    float c1 = hi ? t.w  : t.y;
    float c2 = hi ? bt.z : bt.x;
    float c3 = hi ? bt.w : bt.y;
    float v = c0;
    v = (idx == 1) ? c1 : v;
    v = (idx == 2) ? c2 : v;
    v = (idx == 3) ? c3 : v;
    return v;
}

__global__ __launch_bounds__(256)
void qmap_kernel(const float* __restrict__ x, float* __restrict__ out) {
    int tid = blockIdx.x * blockDim.x + threadIdx.x;
    // total threads = 16 * 64 * 64 * 32 = 2,097,152
    int j   = tid & 31;           // w2-pair: w2 = 2j, 2j+1; input w base = 4j
    int h2  = (tid >> 5)  & 63;
    int c4i = (tid >> 11) & 63;
    int b   = tid >> 17;

    const size_t plane       = (size_t)HH * WW;          // 16384
    const size_t comp_stride = (size_t)NC4 * plane;      // 64*16384

    size_t base = (size_t)(b * 4) * comp_stride
                + (size_t)c4i * plane
                + (size_t)(2 * h2) * WW
                + (size_t)(4 * j);

    // 8 independent 16B loads, front-batched; .cg = no L1 allocation
    float4 r0[4], r1[4];
#pragma unroll
    for (int cm = 0; cm < 4; cm++) {
        const float* p = x + base + (size_t)cm * comp_stride;
        r0[cm] = __ldcg(reinterpret_cast<const float4*>(p));
        r1[cm] = __ldcg(reinterpret_cast<const float4*>(p + WW));
    }

    // amp^2 for pixel lo (r0.xy, r1.xy) and pixel hi (r0.zw, r1.zw)
    float aA[4] = {0.f, 0.f, 0.f, 0.f};
    float aB[4] = {0.f, 0.f, 0.f, 0.f};
#pragma unroll
    for (int cm = 0; cm < 4; cm++) {
        aA[0] = fmaf(r0[cm].x, r0[cm].x, aA[0]);
        aA[1] = fmaf(r0[cm].y, r0[cm].y, aA[1]);
        aA[2] = fmaf(r1[cm].x, r1[cm].x, aA[2]);
        aA[3] = fmaf(r1[cm].y, r1[cm].y, aA[3]);
        aB[0] = fmaf(r0[cm].z, r0[cm].z, aB[0]);
        aB[1] = fmaf(r0[cm].w, r0[cm].w, aB[1]);
        aB[2] = fmaf(r1[cm].z, r1[cm].z, aB[2]);
        aB[3] = fmaf(r1[cm].w, r1[cm].w, aB[3]);
    }

    // first-argmax (strict >) per pixel
    int iA = 0, iB = 0;
    {
        float m = aA[0];
        if (aA[1] > m) { m = aA[1]; iA = 1; }
        if (aA[2] > m) { m = aA[2]; iA = 2; }
        if (aA[3] > m) {            iA = 3; }
    }
    {
        float m = aB[0];
        if (aB[1] > m) { m = aB[1]; iB = 1; }
        if (aB[2] > m) { m = aB[2]; iB = 2; }
        if (aB[3] > m) {            iB = 3; }
    }

    const size_t oplane       = (size_t)H2 * W2;         // 4096
    const size_t ocomp_stride = (size_t)NC4 * oplane;    // 64*4096
    size_t obase = (size_t)(b * 4) * ocomp_stride
                 + (size_t)c4i * oplane
                 + (size_t)h2 * W2
                 + (size_t)(2 * j);

#pragma unroll
    for (int cm = 0; cm < 4; cm++) {
        float vA = pick2x2(r0[cm], r1[cm], iA, false);
        float vB = pick2x2(r0[cm], r1[cm], iB, true);
        __stcs(reinterpret_cast<float2*>(out + obase + (size_t)cm * ocomp_stride),
               make_float2(vA, vB));
    }
}

extern "C" void kernel_launch(void* const* d_in, const int* in_sizes, int n_in,
                              void* d_out, int out_size) {
    const float* x = (const float*)d_in[0];
    float* out = (float*)d_out;
    const int total = NB * NC4 * H2 * (W2 / 2);   // 2,097,152 threads
    const int block = 256;
    const int grid  = total / block;              // 8192
    qmap_kernel<<<grid, block>>>(x, out);
}

// round 11
// speedup vs baseline: 1.0037x; 1.0037x over previous
#include <cuda_runtime.h>

// QuaternionMaxAmpPool2d — FINAL (converged; best measured config, bench 51.296us x2)
//
// x: (16, 256, 128, 128) fp32, c = comp*64 + c4 (comp outer)
// out: (16, 256, 64, 64) fp32
// For each (b, c4, h2, w2): amp2[p] = sum_comp x[b, comp*64+c4, 2h2+kh, 2w2+kw]^2,
// p = kh*2+kw; first argmax p (strict >, sqrt dropped — monotone); emit the 4
// component values at p.
//
// Shape (measured optimal across 10 rounds):
//   - block=256, grid=8192; 2 output pixels per thread (one w2-pair)
//   - per component: 2 front-batched LDG.128 (rows 2h2, 2h2+1); a warp spans
//     a full 512B input row per load slot -> perfect sector coalescing, MLP=8
//   - default-policy loads (policy variants measured neutral/worse)
//   - .cs float2 stores (zero-reuse write stream); warp spans 256B contiguous
//     output per component
// Runs at ~6.7-6.8 TB/s DRAM — the B300 practical streaming ceiling. Axes
// closed by measurement: cache policies, wider per-thread tiles, reg-capped
// occupancy, persistent grid, block=512. All neutral or regressions.

#define NB   16
#define NC4  64
#define HH   128
#define WW   128
#define H2   64
#define W2   64

__device__ __forceinline__ float pick2x2(const float4& t, const float4& bt, int idx, bool hi) {
    float c0 = hi ? t.z  : t.x;
    float c1 = hi ? t.w  : t.y;
    float c2 = hi ? bt.z : bt.x;
    float c3 = hi ? bt.w : bt.y;
    float v = c0;
    v = (idx == 1) ? c1 : v;
    v = (idx == 2) ? c2 : v;
    v = (idx == 3) ? c3 : v;
    return v;
}

__global__ __launch_bounds__(256)
void qmap_kernel(const float* __restrict__ x, float* __restrict__ out) {
    int tid = blockIdx.x * blockDim.x + threadIdx.x;
    // total threads = 16 * 64 * 64 * 32 = 2,097,152
    int j   = tid & 31;           // w2-pair: w2 = 2j, 2j+1; input w base = 4j
    int h2  = (tid >> 5)  & 63;
    int c4i = (tid >> 11) & 63;
    int b   = tid >> 17;

    const size_t plane       = (size_t)HH * WW;          // 16384
    const size_t comp_stride = (size_t)NC4 * plane;      // 64*16384

    size_t base = (size_t)(b * 4) * comp_stride
                + (size_t)c4i * plane
                + (size_t)(2 * h2) * WW
                + (size_t)(4 * j);

    // 8 independent 16B loads, front-batched for MLP
    float4 r0[4], r1[4];
#pragma unroll
    for (int cm = 0; cm < 4; cm++) {
        const float* p = x + base + (size_t)cm * comp_stride;
        r0[cm] = *reinterpret_cast<const float4*>(p);
        r1[cm] = *reinterpret_cast<const float4*>(p + WW);
    }

    // amp^2 for pixel lo (r0.xy, r1.xy) and pixel hi (r0.zw, r1.zw)
    float aA[4] = {0.f, 0.f, 0.f, 0.f};
    float aB[4] = {0.f, 0.f, 0.f, 0.f};
#pragma unroll
    for (int cm = 0; cm < 4; cm++) {
        aA[0] = fmaf(r0[cm].x, r0[cm].x, aA[0]);
        aA[1] = fmaf(r0[cm].y, r0[cm].y, aA[1]);
        aA[2] = fmaf(r1[cm].x, r1[cm].x, aA[2]);
        aA[3] = fmaf(r1[cm].y, r1[cm].y, aA[3]);
        aB[0] = fmaf(r0[cm].z, r0[cm].z, aB[0]);
        aB[1] = fmaf(r0[cm].w, r0[cm].w, aB[1]);
        aB[2] = fmaf(r1[cm].z, r1[cm].z, aB[2]);
        aB[3] = fmaf(r1[cm].w, r1[cm].w, aB[3]);
    }

    // first-argmax (strict >) per pixel
    int iA = 0, iB = 0;
    {
        float m = aA[0];
        if (aA[1] > m) { m = aA[1]; iA = 1; }
        if (aA[2] > m) { m = aA[2]; iA = 2; }
        if (aA[3] > m) {            iA = 3; }
    }
    {
        float m = aB[0];
        if (aB[1] > m) { m = aB[1]; iB = 1; }
        if (aB[2] > m) { m = aB[2]; iB = 2; }
        if (aB[3] > m) {            iB = 3; }
    }

    const size_t oplane       = (size_t)H2 * W2;         // 4096
    const size_t ocomp_stride = (size_t)NC4 * oplane;    // 64*4096
    size_t obase = (size_t)(b * 4) * ocomp_stride
                 + (size_t)c4i * oplane
                 + (size_t)h2 * W2
                 + (size_t)(2 * j);

#pragma unroll
    for (int cm = 0; cm < 4; cm++) {
        float vA = pick2x2(r0[cm], r1[cm], iA, false);
        float vB = pick2x2(r0[cm], r1[cm], iB, true);
        // streaming store: evict-first, keep L2 capacity for the read stream
        __stcs(reinterpret_cast<float2*>(out + obase + (size_t)cm * ocomp_stride),
               make_float2(vA, vB));
    }
}

extern "C" void kernel_launch(void* const* d_in, const int* in_sizes, int n_in,
                              void* d_out, int out_size) {
    const float* x = (const float*)d_in[0];
    float* out = (float*)d_out;
    const int total = NB * NC4 * H2 * (W2 / 2);   // 2,097,152 threads
    const int block = 256;
    const int grid  = total / block;              // 8192
    qmap_kernel<<<grid, block>>>(x, out);
}

// round 12
// speedup vs baseline: 1.0144x; 1.0106x over previous
#include <cuda_runtime.h>

// QuaternionMaxAmpPool2d — converged body (R3/R9/R11); this round: block=128
// (16384 CTAs) for finer tail-wave packing. Warp-level memory behavior is
// identical to the measured-best config (coalescing/MLP are warp properties).
//
// x: (16, 256, 128, 128) fp32, c = comp*64 + c4 (comp outer)
// out: (16, 256, 64, 64) fp32
// For each (b, c4, h2, w2): amp2[p] = sum_comp x[b, comp*64+c4, 2h2+kh, 2w2+kw]^2,
// p = kh*2+kw; first argmax p (strict >, sqrt dropped — monotone); emit the 4
// component values at p.

#define NB   16
#define NC4  64
#define HH   128
#define WW   128
#define H2   64
#define W2   64

__device__ __forceinline__ float pick2x2(const float4& t, const float4& bt, int idx, bool hi) {
    float c0 = hi ? t.z  : t.x;
    float c1 = hi ? t.w  : t.y;
    float c2 = hi ? bt.z : bt.x;
    float c3 = hi ? bt.w : bt.y;
    float v = c0;
    v = (idx == 1) ? c1 : v;
    v = (idx == 2) ? c2 : v;
    v = (idx == 3) ? c3 : v;
    return v;
}

__global__ __launch_bounds__(128)
void qmap_kernel(const float* __restrict__ x, float* __restrict__ out) {
    int tid = blockIdx.x * blockDim.x + threadIdx.x;
    // total threads = 16 * 64 * 64 * 32 = 2,097,152
    int j   = tid & 31;           // w2-pair: w2 = 2j, 2j+1; input w base = 4j
    int h2  = (tid >> 5)  & 63;
    int c4i = (tid >> 11) & 63;
    int b   = tid >> 17;

    const size_t plane       = (size_t)HH * WW;          // 16384
    const size_t comp_stride = (size_t)NC4 * plane;      // 64*16384

    size_t base = (size_t)(b * 4) * comp_stride
                + (size_t)c4i * plane
                + (size_t)(2 * h2) * WW
                + (size_t)(4 * j);

    // 8 independent 16B loads, front-batched for MLP
    float4 r0[4], r1[4];
#pragma unroll
    for (int cm = 0; cm < 4; cm++) {
        const float* p = x + base + (size_t)cm * comp_stride;
        r0[cm] = *reinterpret_cast<const float4*>(p);
        r1[cm] = *reinterpret_cast<const float4*>(p + WW);
    }

    // amp^2 for pixel lo (r0.xy, r1.xy) and pixel hi (r0.zw, r1.zw)
    float aA[4] = {0.f, 0.f, 0.f, 0.f};
    float aB[4] = {0.f, 0.f, 0.f, 0.f};
#pragma unroll
    for (int cm = 0; cm < 4; cm++) {
        aA[0] = fmaf(r0[cm].x, r0[cm].x, aA[0]);
        aA[1] = fmaf(r0[cm].y, r0[cm].y, aA[1]);
        aA[2] = fmaf(r1[cm].x, r1[cm].x, aA[2]);
        aA[3] = fmaf(r1[cm].y, r1[cm].y, aA[3]);
        aB[0] = fmaf(r0[cm].z, r0[cm].z, aB[0]);
        aB[1] = fmaf(r0[cm].w, r0[cm].w, aB[1]);
        aB[2] = fmaf(r1[cm].z, r1[cm].z, aB[2]);
        aB[3] = fmaf(r1[cm].w, r1[cm].w, aB[3]);
    }

    // first-argmax (strict >) per pixel
    int iA = 0, iB = 0;
    {
        float m = aA[0];
        if (aA[1] > m) { m = aA[1]; iA = 1; }
        if (aA[2] > m) { m = aA[2]; iA = 2; }
        if (aA[3] > m) {            iA = 3; }
    }
    {
        float m = aB[0];
        if (aB[1] > m) { m = aB[1]; iB = 1; }
        if (aB[2] > m) { m = aB[2]; iB = 2; }
        if (aB[3] > m) {            iB = 3; }
    }

    const size_t oplane       = (size_t)H2 * W2;         // 4096
    const size_t ocomp_stride = (size_t)NC4 * oplane;    // 64*4096
    size_t obase = (size_t)(b * 4) * ocomp_stride
                 + (size_t)c4i * oplane
                 + (size_t)h2 * W2
                 + (size_t)(2 * j);

#pragma unroll
    for (int cm = 0; cm < 4; cm++) {
        float vA = pick2x2(r0[cm], r1[cm], iA, false);
        float vB = pick2x2(r0[cm], r1[cm], iB, true);
        // streaming store: evict-first, keep L2 capacity for the read stream
        __stcs(reinterpret_cast<float2*>(out + obase + (size_t)cm * ocomp_stride),
               make_float2(vA, vB));
    }
}

extern "C" void kernel_launch(void* const* d_in, const int* in_sizes, int n_in,
                              void* d_out, int out_size) {
    const float* x = (const float*)d_in[0];
    float* out = (float*)d_out;
    const int total = NB * NC4 * H2 * (W2 / 2);   // 2,097,152 threads
    const int block = 128;
    const int grid  = total / block;              // 16384
    qmap_kernel<<<grid, block>>>(x, out);
}